// round 3
// baseline (speedup 1.0000x reference)
#include <cuda_runtime.h>
#include <cuda_bf16.h>
#include <mma.h>
#include <cstdint>

using namespace nvcuda;
using bf16 = __nv_bfloat16;
#define DEV __device__ __forceinline__

static constexpr int NN = 8192;   // nodes
static constexpr int FI = 256;    // in features
static constexpr int FO = 256;    // out features
static constexpr int KW = 512;    // split-W contraction dim (W_hi | W_lo)

// GEMM tiling (wmma path)
static constexpr int TM   = 128;
static constexpr int TN   = 128;
static constexpr int KC   = 32;                 // K elems per stage
static constexpr int SROW = 40;                 // padded smem row (elems) = 80 B
static constexpr int TILE_B  = TM * SROW * 2;   // 10240 B per operand tile
static constexpr int STAGE_B = 2 * TILE_B;      // 20480 B (A + B)
static constexpr int S = 3;
static constexpr int SMEM_SZ = S * STAGE_B;     // 61440 B

// ---------------- scratch (device globals; no runtime allocation) -----------
__device__ float g_dis[NN];
__device__ bf16  g_Abf[(size_t)NN * NN];   // bf16(A + I)
__device__ bf16  g_X2[(size_t)NN * KW];    // [ d^-1/2 X | d^-1/2 X ]  rows j, K-contig
__device__ bf16  g_W2[(size_t)FO * KW];    // [ W_hi | W_lo ]          rows f, K-contig
__device__ bf16  g_Pt[(size_t)FO * NN];    // Pt[f][j], j contiguous
__device__ float g_C[(size_t)NN * FO];     // fp32 GEMM scratch (reused by both GEMMs)

// ---------------- helpers ----------------
DEV uint32_t smem_u32(const void* p) {
    uint32_t a;
    asm("{ .reg .u64 t; cvta.to.shared.u64 t, %1; cvt.u32.u64 %0, t; }" : "=r"(a) : "l"(p));
    return a;
}
DEV void cp16(uint32_t s, const void* g) {
    asm volatile("cp.async.cg.shared.global [%0], [%1], 16;" :: "r"(s), "l"(g));
}
DEV void cp_commit() { asm volatile("cp.async.commit_group;" ::: "memory"); }

// ========================== prep: deg + bf16(A+I) ==========================
__global__ void __launch_bounds__(256) k_prep(const float* __restrict__ A) {
    const int row = blockIdx.x;
    const float4* A4 = reinterpret_cast<const float4*>(A + (size_t)row * NN);
    uint2* O = reinterpret_cast<uint2*>(g_Abf + (size_t)row * NN);

    float sum = 0.f;
#pragma unroll
    for (int u = 0; u < 8; u++) {
        const int p4 = threadIdx.x + u * 256;    // 0..2047
        float4 v = A4[p4];
        const int d = row - p4 * 4;
        if (d >= 0 && d < 4) {                   // add identity before quantizing
            if      (d == 0) v.x += 1.f;
            else if (d == 1) v.y += 1.f;
            else if (d == 2) v.z += 1.f;
            else             v.w += 1.f;
        }
        sum += (v.x + v.y) + (v.z + v.w);
        __nv_bfloat162 lo = __floats2bfloat162_rn(v.x, v.y);
        __nv_bfloat162 hi = __floats2bfloat162_rn(v.z, v.w);
        uint2 st;
        st.x = *reinterpret_cast<uint32_t*>(&lo);
        st.y = *reinterpret_cast<uint32_t*>(&hi);
        O[p4] = st;
    }
    __shared__ float red[256];
    red[threadIdx.x] = sum;
    __syncthreads();
#pragma unroll
    for (int off = 128; off > 0; off >>= 1) {
        if (threadIdx.x < off) red[threadIdx.x] += red[threadIdx.x + off];
        __syncthreads();
    }
    if (threadIdx.x == 0) g_dis[row] = rsqrtf(red[0]);
}

// ================ quant: X2 = [ds*X | ds*X], W2 = [W_hi | W_lo] ============
__global__ void __launch_bounds__(256) k_x2(const float* __restrict__ X) {
    const int row = blockIdx.x, c = threadIdx.x;
    const float s = g_dis[row];
    const bf16 v = __float2bfloat16(s * X[(size_t)row * FI + c]);
    g_X2[(size_t)row * KW + c]      = v;
    g_X2[(size_t)row * KW + FI + c] = v;
}
__global__ void __launch_bounds__(256) k_w2(const float* __restrict__ W) {
    const int f = blockIdx.x, c = threadIdx.x;
    const float w = W[(size_t)f * FI + c];
    const bf16 hi = __float2bfloat16(w);
    const bf16 lo = __float2bfloat16(w - __bfloat162float(hi));
    g_W2[(size_t)f * KW + c]      = hi;
    g_W2[(size_t)f * KW + FI + c] = lo;
}

// ============== quant Pt (bf16) from GEMM1 fp32 result =====================
__global__ void __launch_bounds__(256) k_qpt() {
    const int idx = blockIdx.x * 256 + threadIdx.x;          // over fp32 pairs
    const float2 v = reinterpret_cast<const float2*>(g_C)[idx];
    __nv_bfloat162 h = __floats2bfloat162_rn(v.x, v.y);
    reinterpret_cast<uint32_t*>(g_Pt)[idx] = *reinterpret_cast<uint32_t*>(&h);
}

// ============== final epilogue: out = dis[i]*C[i][f] + b[f] ================
__global__ void __launch_bounds__(256) k_ep(float* __restrict__ out,
                                            const float* __restrict__ bias) {
    const int i = blockIdx.x, f = threadIdx.x;
    out[(size_t)i * FO + f] = g_dis[i] * g_C[(size_t)i * FO + f] + bias[f];
}

// ========================== wmma bf16 GEMM =================================
// C[m0+m, n0+n] = sum_k Aop[m0+m, k] * Bop[n0+n, k]   (both K-contiguous bf16)
DEV void load_tile(uint32_t sdst, const bf16* __restrict__ g, int row0,
                   int ktot, int k0) {
#pragma unroll
    for (int t = 0; t < 4; t++) {
        const int c = threadIdx.x + t * 128;     // 0..511 chunks of 16 B
        const int row = c >> 2, off = (c & 3) * 16;
        const uint32_t s = sdst + (uint32_t)(row * 80 + off);
        const char* src =
            reinterpret_cast<const char*>(g + (size_t)(row0 + row) * ktot + k0) + off;
        cp16(s, src);
    }
}

__global__ void __launch_bounds__(128, 1)
k_gemm(const bf16* __restrict__ Ao, const bf16* __restrict__ Bo,
       int ktot, int nk, float* __restrict__ C, int ldo)
{
    extern __shared__ char smem[];
    const uint32_t sb = smem_u32(smem);
    const int wid = threadIdx.x >> 5;
    const int wm = wid & 1, wn = wid >> 1;       // 2x2 warp grid of 64x64 tiles
    const int m0 = blockIdx.x * TM, n0 = blockIdx.y * TN;

    wmma::fragment<wmma::accumulator, 16, 16, 16, float> acc[4][4];
#pragma unroll
    for (int i = 0; i < 4; i++)
#pragma unroll
        for (int j = 0; j < 4; j++) wmma::fill_fragment(acc[i][j], 0.f);

    // prologue: stages 0,1
#pragma unroll
    for (int s = 0; s < S - 1; s++) {
        load_tile(sb + s * STAGE_B, Ao, m0, ktot, s * KC);
        load_tile(sb + s * STAGE_B + TILE_B, Bo, n0, ktot, s * KC);
        cp_commit();
    }

    for (int k = 0; k < nk; k++) {
        if (k + 2 < nk) {
            const int s = (k + 2) % S;
            load_tile(sb + s * STAGE_B, Ao, m0, ktot, (k + 2) * KC);
            load_tile(sb + s * STAGE_B + TILE_B, Bo, n0, ktot, (k + 2) * KC);
        }
        cp_commit();
        asm volatile("cp.async.wait_group 2;" ::: "memory");
        __syncthreads();

        const bf16* sa = reinterpret_cast<const bf16*>(smem + (k % S) * STAGE_B);
        const bf16* sbp = reinterpret_cast<const bf16*>(smem + (k % S) * STAGE_B + TILE_B);
#pragma unroll
        for (int kk = 0; kk < KC / 16; kk++) {
            wmma::fragment<wmma::matrix_a, 16, 16, 16, bf16, wmma::row_major> fa[4];
            wmma::fragment<wmma::matrix_b, 16, 16, 16, bf16, wmma::col_major> fb[4];
#pragma unroll
            for (int i = 0; i < 4; i++)
                wmma::load_matrix_sync(fa[i], sa + (wm * 64 + i * 16) * SROW + kk * 16, SROW);
#pragma unroll
            for (int j = 0; j < 4; j++)
                wmma::load_matrix_sync(fb[j], sbp + (wn * 64 + j * 16) * SROW + kk * 16, SROW);
#pragma unroll
            for (int i = 0; i < 4; i++)
#pragma unroll
                for (int j = 0; j < 4; j++)
                    wmma::mma_sync(acc[i][j], fa[i], fb[j], acc[i][j]);
        }
        __syncthreads();
    }

#pragma unroll
    for (int i = 0; i < 4; i++)
#pragma unroll
        for (int j = 0; j < 4; j++) {
            float* dst = C + (size_t)(m0 + wm * 64 + i * 16) * ldo + n0 + wn * 64 + j * 16;
            wmma::store_matrix_sync(dst, acc[i][j], ldo, wmma::mem_row_major);
        }
}

// ================================ launch ===================================
extern "C" void kernel_launch(void* const* d_in, const int* in_sizes, int n_in,
                              void* d_out, int out_size) {
    const float* X = (const float*)d_in[0];
    const float* A = (const float*)d_in[1];
    const float* W = (const float*)d_in[2];
    const float* b = (const float*)d_in[3];
    float* out = (float*)d_out;

    cudaFuncSetAttribute(k_gemm, cudaFuncAttributeMaxDynamicSharedMemorySize, SMEM_SZ);

    bf16 *Abf, *X2, *W2, *Pt;
    float* Cs;
    cudaGetSymbolAddress((void**)&Abf, g_Abf);
    cudaGetSymbolAddress((void**)&X2,  g_X2);
    cudaGetSymbolAddress((void**)&W2,  g_W2);
    cudaGetSymbolAddress((void**)&Pt,  g_Pt);
    cudaGetSymbolAddress((void**)&Cs,  g_C);

    k_prep<<<NN, 256>>>(A);
    k_x2<<<NN, 256>>>(X);
    k_w2<<<FO, 256>>>(W);
    // GEMM1: C[f, j] = sum_k W2[f,k] * X2[j,k]   M=FO, N=NN, K=KW
    k_gemm<<<dim3(FO / TM, NN / TN), 128, SMEM_SZ>>>(W2, X2, KW, KW / KC, Cs, NN);
    k_qpt<<<(FO * NN / 2) / 256, 256>>>();
    // GEMM2: C[i, f] = sum_j Abf[i,j] * Pt[f,j]  M=NN, N=FO, K=NN
    k_gemm<<<dim3(NN / TM, FO / TN), 128, SMEM_SZ>>>(Abf, Pt, NN, NN / KC, Cs, FO);
    k_ep<<<NN, 256>>>(out, b);
}

// round 4
// speedup vs baseline: 1.0467x; 1.0467x over previous
#include <cuda_runtime.h>
#include <cuda_bf16.h>
#include <mma.h>
#include <cstdint>

using namespace nvcuda;
using bf16 = __nv_bfloat16;
#define DEV __device__ __forceinline__

static constexpr int NN = 8192;   // nodes
static constexpr int FI = 256;    // in features
static constexpr int FO = 256;    // out features
static constexpr int KW = 512;    // split-W contraction dim (W_hi | W_lo)

// GEMM tiling
static constexpr int TM   = 128;
static constexpr int TN   = 128;
static constexpr int KC   = 64;                  // K elems per stage
static constexpr int SROW = 72;                  // padded smem row (elems) = 144 B
static constexpr int TILE_B  = TM * SROW * 2;    // 18432 B per operand tile
static constexpr int STAGE_B = 2 * TILE_B;       // 36864 B (A + B)
static constexpr int S = 3;
static constexpr int SMEM_SZ = S * STAGE_B;      // 110592 B
// epilogue smem: 128 x 132 fp32 = 67584 B (fits inside SMEM_SZ, reused)
static constexpr int EROW = 132;

// warp tiling: 8 warps in 4x2 grid, each 32(m) x 64(n) -> 2x4 fragments
// ---------------- scratch (device globals; no runtime allocation) -----------
__device__ float g_dis[NN];
__device__ bf16  g_Abf[(size_t)NN * NN];   // bf16(A + I)
__device__ bf16  g_X2[(size_t)NN * KW];    // [ d^-1/2 X | d^-1/2 X ]  rows j, K-contig
__device__ bf16  g_W2[(size_t)FO * KW];    // [ W_hi | W_lo ]          rows f, K-contig
__device__ bf16  g_Pt[(size_t)FO * NN];    // Pt[f][j], j contiguous

// ---------------- helpers ----------------
DEV uint32_t smem_u32(const void* p) {
    uint32_t a;
    asm("{ .reg .u64 t; cvta.to.shared.u64 t, %1; cvt.u32.u64 %0, t; }" : "=r"(a) : "l"(p));
    return a;
}
DEV void cp16(uint32_t s, const void* g) {
    asm volatile("cp.async.cg.shared.global [%0], [%1], 16;" :: "r"(s), "l"(g));
}
DEV void cp_commit() { asm volatile("cp.async.commit_group;" ::: "memory"); }

// ========================== prep: deg + bf16(A+I) ==========================
__global__ void __launch_bounds__(256) k_prep(const float* __restrict__ A) {
    const int row = blockIdx.x;
    const float4* A4 = reinterpret_cast<const float4*>(A + (size_t)row * NN);
    uint2* O = reinterpret_cast<uint2*>(g_Abf + (size_t)row * NN);

    float sum = 0.f;
#pragma unroll
    for (int u = 0; u < 8; u++) {
        const int p4 = threadIdx.x + u * 256;    // 0..2047
        float4 v = A4[p4];
        const int d = row - p4 * 4;
        if (d >= 0 && d < 4) {                   // add identity before quantizing
            if      (d == 0) v.x += 1.f;
            else if (d == 1) v.y += 1.f;
            else if (d == 2) v.z += 1.f;
            else             v.w += 1.f;
        }
        sum += (v.x + v.y) + (v.z + v.w);
        __nv_bfloat162 lo = __floats2bfloat162_rn(v.x, v.y);
        __nv_bfloat162 hi = __floats2bfloat162_rn(v.z, v.w);
        uint2 st;
        st.x = *reinterpret_cast<uint32_t*>(&lo);
        st.y = *reinterpret_cast<uint32_t*>(&hi);
        O[p4] = st;
    }
    __shared__ float red[256];
    red[threadIdx.x] = sum;
    __syncthreads();
#pragma unroll
    for (int off = 128; off > 0; off >>= 1) {
        if (threadIdx.x < off) red[threadIdx.x] += red[threadIdx.x + off];
        __syncthreads();
    }
    if (threadIdx.x == 0) g_dis[row] = rsqrtf(red[0]);
}

// ================ quant: X2 = [ds*X | ds*X], W2 = [W_hi | W_lo] ============
__global__ void __launch_bounds__(256) k_x2(const float* __restrict__ X) {
    const int row = blockIdx.x, c = threadIdx.x;
    const float s = g_dis[row];
    const bf16 v = __float2bfloat16(s * X[(size_t)row * FI + c]);
    g_X2[(size_t)row * KW + c]      = v;
    g_X2[(size_t)row * KW + FI + c] = v;
}
__global__ void __launch_bounds__(256) k_w2(const float* __restrict__ W) {
    const int f = blockIdx.x, c = threadIdx.x;
    const float w = W[(size_t)f * FI + c];
    const bf16 hi = __float2bfloat16(w);
    const bf16 lo = __float2bfloat16(w - __bfloat162float(hi));
    g_W2[(size_t)f * KW + c]      = hi;
    g_W2[(size_t)f * KW + FI + c] = lo;
}

// ========================== wmma bf16 GEMM =================================
// acc[m0+m, n0+n] = sum_k Aop[m0+m, k] * Bop[n0+n, k]  (both K-contiguous bf16)
// mode 0: outB[(m)*ldo + n] = bf16(acc)
// mode 1: outF[(m)*ldo + n] = dis[m]*acc + bias[n]
DEV void load_tile(uint32_t sdst, const bf16* __restrict__ g, int row0,
                   int ktot, int k0) {
#pragma unroll
    for (int t = 0; t < 4; t++) {
        const int c = threadIdx.x + t * 256;     // 0..1023 chunks of 16 B
        const int row = c >> 3, off = (c & 7) * 16;
        const uint32_t s = sdst + (uint32_t)(row * (SROW * 2) + off);
        const char* src =
            reinterpret_cast<const char*>(g + (size_t)(row0 + row) * ktot + k0) + off;
        cp16(s, src);
    }
}

__global__ void __launch_bounds__(256, 1)
k_gemm(const bf16* __restrict__ Ao, const bf16* __restrict__ Bo,
       int ktot, int nk, float* __restrict__ outF, bf16* __restrict__ outB,
       const float* __restrict__ dis, const float* __restrict__ bias,
       int ldo, int mode)
{
    extern __shared__ char smem[];
    const uint32_t sb = smem_u32(smem);
    const int wid = threadIdx.x >> 5;
    const int wm = wid & 3, wn = wid >> 2;       // 4x2 warp grid of 32x64 tiles
    const int m0 = blockIdx.x * TM, n0 = blockIdx.y * TN;

    wmma::fragment<wmma::accumulator, 16, 16, 16, float> acc[2][4];
#pragma unroll
    for (int i = 0; i < 2; i++)
#pragma unroll
        for (int j = 0; j < 4; j++) wmma::fill_fragment(acc[i][j], 0.f);

    // prologue: stages 0,1
#pragma unroll
    for (int s = 0; s < S - 1; s++) {
        load_tile(sb + s * STAGE_B, Ao, m0, ktot, s * KC);
        load_tile(sb + s * STAGE_B + TILE_B, Bo, n0, ktot, s * KC);
        cp_commit();
    }

    for (int k = 0; k < nk; k++) {
        asm volatile("cp.async.wait_group 1;" ::: "memory");   // stage k resident
        __syncthreads();   // stage k visible to all; stage (k+2)%S fully consumed

        if (k + 2 < nk) {
            const int s = (k + 2) % S;
            load_tile(sb + s * STAGE_B, Ao, m0, ktot, (k + 2) * KC);
            load_tile(sb + s * STAGE_B + TILE_B, Bo, n0, ktot, (k + 2) * KC);
        }
        cp_commit();

        const bf16* sa  = reinterpret_cast<const bf16*>(smem + (k % S) * STAGE_B);
        const bf16* sbp = reinterpret_cast<const bf16*>(smem + (k % S) * STAGE_B + TILE_B);
#pragma unroll
        for (int kk = 0; kk < KC / 16; kk++) {
            wmma::fragment<wmma::matrix_a, 16, 16, 16, bf16, wmma::row_major> fa[2];
            wmma::fragment<wmma::matrix_b, 16, 16, 16, bf16, wmma::col_major> fb[4];
#pragma unroll
            for (int i = 0; i < 2; i++)
                wmma::load_matrix_sync(fa[i], sa + (wm * 32 + i * 16) * SROW + kk * 16, SROW);
#pragma unroll
            for (int j = 0; j < 4; j++)
                wmma::load_matrix_sync(fb[j], sbp + (wn * 64 + j * 16) * SROW + kk * 16, SROW);
#pragma unroll
            for (int i = 0; i < 2; i++)
#pragma unroll
                for (int j = 0; j < 4; j++)
                    wmma::mma_sync(acc[i][j], fa[i], fb[j], acc[i][j]);
        }
    }

    // ------------- epilogue via smem roundtrip -------------
    __syncthreads();
    float* es = reinterpret_cast<float*>(smem);
#pragma unroll
    for (int i = 0; i < 2; i++)
#pragma unroll
        for (int j = 0; j < 4; j++)
            wmma::store_matrix_sync(es + (size_t)(wm * 32 + i * 16) * EROW + wn * 64 + j * 16,
                                    acc[i][j], EROW, wmma::mem_row_major);
    __syncthreads();

    const int tid = threadIdx.x;
    if (mode == 0) {
#pragma unroll
        for (int t = 0; t < 16; t++) {
            const int e = tid + t * 256;                 // 0..4095 groups of 4 elems
            const int row = e >> 5, c4 = (e & 31) * 4;
            const float* src = es + (size_t)row * EROW + c4;
            __nv_bfloat162 h0 = __floats2bfloat162_rn(src[0], src[1]);
            __nv_bfloat162 h1 = __floats2bfloat162_rn(src[2], src[3]);
            uint2 st;
            st.x = *reinterpret_cast<uint32_t*>(&h0);
            st.y = *reinterpret_cast<uint32_t*>(&h1);
            *reinterpret_cast<uint2*>(outB + (size_t)(m0 + row) * ldo + n0 + c4) = st;
        }
    } else {
#pragma unroll
        for (int t = 0; t < 16; t++) {
            const int e = tid + t * 256;
            const int row = e >> 5, c4 = (e & 31) * 4;
            const float sc = dis[m0 + row];
            const float* src = es + (size_t)row * EROW + c4;
            float4 v;
            v.x = sc * src[0] + bias[n0 + c4 + 0];
            v.y = sc * src[1] + bias[n0 + c4 + 1];
            v.z = sc * src[2] + bias[n0 + c4 + 2];
            v.w = sc * src[3] + bias[n0 + c4 + 3];
            *reinterpret_cast<float4*>(outF + (size_t)(m0 + row) * ldo + n0 + c4) = v;
        }
    }
}

// ================================ launch ===================================
extern "C" void kernel_launch(void* const* d_in, const int* in_sizes, int n_in,
                              void* d_out, int out_size) {
    const float* X = (const float*)d_in[0];
    const float* A = (const float*)d_in[1];
    const float* W = (const float*)d_in[2];
    const float* b = (const float*)d_in[3];
    float* out = (float*)d_out;

    cudaFuncSetAttribute(k_gemm, cudaFuncAttributeMaxDynamicSharedMemorySize, SMEM_SZ);

    bf16 *Abf, *X2, *W2, *Pt;
    float* dis;
    cudaGetSymbolAddress((void**)&Abf, g_Abf);
    cudaGetSymbolAddress((void**)&X2,  g_X2);
    cudaGetSymbolAddress((void**)&W2,  g_W2);
    cudaGetSymbolAddress((void**)&Pt,  g_Pt);
    cudaGetSymbolAddress((void**)&dis, g_dis);

    k_prep<<<NN, 256>>>(A);
    k_x2<<<NN, 256>>>(X);
    k_w2<<<FO, 256>>>(W);
    // GEMM1: Pt[f, j] = bf16( sum_k W2[f,k] * X2[j,k] )   M=FO, N=NN, K=KW
    k_gemm<<<dim3(FO / TM, NN / TN), 256, SMEM_SZ>>>(
        W2, X2, KW, KW / KC, nullptr, Pt, nullptr, nullptr, NN, 0);
    // GEMM2: out[i, f] = dis[i] * sum_j Abf[i,j] * Pt[f,j] + b[f]  M=NN, N=FO, K=NN
    k_gemm<<<dim3(NN / TM, FO / TN), 256, SMEM_SZ>>>(
        Abf, Pt, NN, NN / KC, out, nullptr, dis, b, FO, 1);
}